// round 15
// baseline (speedup 1.0000x reference)
#include <cuda_runtime.h>
#include <cuda_fp16.h>
#include <math.h>
#include <stdint.h>

#define SEQ 2048
#define DM  1024
#define NB  4

static constexpr size_t NQ  = (size_t)NB * SEQ * DM;    //  8388608
static constexpr size_t NSS = (size_t)NB * SEQ * SEQ;   // 16777216
static constexpr size_t NP  = (size_t)SEQ * DM;         //  2097152
static constexpr size_t NU  = (size_t)DM * DM;          //  1048576

// ---- scratch (static device globals; no allocation) ----
__device__ __half g_qhi[NQ];
__device__ __half g_khi[NQ];
__device__ __half g_vthi[NQ];
__device__ __half g_ahi[NSS];
__device__ __half g_pehi[NP];
__device__ __half g_uqt[NU],  g_ukt[NU];
__device__ __half g_qpe[NP],  g_kpe[NP];
__device__ float  g_bias[(size_t)SEQ * SEQ];
__device__ float  g_scores[NSS];

// ------------------------------- PTX helpers -------------------------------
__device__ __forceinline__ uint32_t s2u(const void* p) {
    uint32_t a;
    asm("{ .reg .u64 t; cvta.to.shared.u64 t, %1; cvt.u32.u64 %0, t; }"
        : "=r"(a) : "l"(p));
    return a;
}
__device__ __forceinline__ void cpa16(uint32_t dst, const void* src) {
    asm volatile("cp.async.cg.shared.global [%0], [%1], 16;" :: "r"(dst), "l"(src) : "memory");
}
#define LDSM4(r, addr) \
    asm volatile("ldmatrix.sync.aligned.m8n8.x4.shared.b16 {%0,%1,%2,%3}, [%4];" \
        : "=r"((r)[0]), "=r"((r)[1]), "=r"((r)[2]), "=r"((r)[3]) : "r"(addr))
#define MMA_F16_F32(d, a, b0, b1) \
    asm volatile("mma.sync.aligned.m16n8k16.row.col.f32.f16.f16.f32 " \
        "{%0,%1,%2,%3}, {%4,%5,%6,%7}, {%8,%9}, {%0,%1,%2,%3};" \
        : "+f"((d)[0]), "+f"((d)[1]), "+f"((d)[2]), "+f"((d)[3]) \
        : "r"((a)[0]), "r"((a)[1]), "r"((a)[2]), "r"((a)[3]), "r"(b0), "r"(b1))

// ---------------------------------------------------------------------------
// fp16 HMMA GEMM (single pass): C[M,N] = alpha * (A @ B^T [+ bias])
//   OUTMODE: 0 = fp32 row-major (+bias, *alpha); 1 = fp16 row-major
//   CTA tile 128x128, BK=32, 256 threads (8 warps, warp tile 32x64),
//   2-stage cp.async pipeline, 80B-padded SMEM rows (conflict-free ldmatrix),
//   3 CTAs/SM (register-trimmed inner loop: B frags loaded just-in-time).
// ---------------------------------------------------------------------------
template<int OUTMODE>
__global__ void __launch_bounds__(256, 3)
hgemm(const __half* __restrict__ A, const __half* __restrict__ B,
      void* __restrict__ Cp, const float* __restrict__ bias, int Kt, int Ng,
      long long aStr, long long bStr, long long cStr, float alpha)
{
    extern __shared__ __align__(128) char smem[];
    constexpr int RSTRIDE = 80;                     // 32 f16 + 16B pad
    constexpr int TSZ = 128 * RSTRIDE;              // 10240 B per tile
    constexpr int STAGE = 2 * TSZ;

    const uint32_t sb = s2u(smem);
    const int tid = threadIdx.x;
    const int lane = tid & 31;
    const int wid = tid >> 5;
    const int warp_m = wid & 3;                      // 4 warps along M
    const int warp_n = wid >> 2;                     // 2 warps along N
    const int bm = blockIdx.y * 128, bn = blockIdx.x * 128, bz = blockIdx.z;
    const int NC = Kt >> 5;                          // chunks of BK=32

    const __half* Ab = A + (long long)bz * aStr;
    const __half* Bb = B + (long long)bz * bStr;

    auto load_chunk = [&](int c) {
        const uint32_t stg = sb + (c & 1) * STAGE;
        const long long kc = (long long)c << 5;
        #pragma unroll
        for (int it = 0; it < 4; it++) {
            const int idx = tid + it * 256;          // 1024 chunks of 16B
            const int t4  = idx >> 9;                // 0=A, 1=B
            const int r   = (idx >> 2) & 127;        // row in tile
            const int c16 = idx & 3;                 // 16B chunk in row
            const __half* src = t4 ? Bb : Ab;
            const int rowg = (t4 ? bn : bm) + r;
            cpa16(stg + t4 * TSZ + r * RSTRIDE + c16 * 16,
                  src + (long long)rowg * Kt + kc + c16 * 8);
        }
        asm volatile("cp.async.commit_group;" ::: "memory");
    };

    float acc[2][8][4];
    #pragma unroll
    for (int f = 0; f < 2; f++)
        #pragma unroll
        for (int j = 0; j < 8; j++)
            #pragma unroll
            for (int e = 0; e < 4; e++) acc[f][j][e] = 0.f;

    load_chunk(0);

    const int lrow = lane & 15;
    const int lkof = (lane >> 4) * 16;               // bytes

    for (int c = 0; c < NC; c++) {
        if (c + 1 < NC) {
            load_chunk(c + 1);
            asm volatile("cp.async.wait_group 1;" ::: "memory");
        } else {
            asm volatile("cp.async.wait_group 0;" ::: "memory");
        }
        __syncthreads();
        const uint32_t stg = sb + (c & 1) * STAGE;
        const uint32_t aOff = stg + (warp_m * 32 + lrow) * RSTRIDE + lkof;
        const uint32_t bOff = stg + TSZ + (warp_n * 64 + lrow) * RSTRIDE + lkof;
        #pragma unroll
        for (int ks = 0; ks < 2; ks++) {
            const uint32_t kb = ks * 32;             // 16 elems = 32 bytes
            uint32_t ah[2][4];
            #pragma unroll
            for (int f = 0; f < 2; f++) LDSM4(ah[f], aOff + f * 16 * RSTRIDE + kb);
            // B fragments loaded just-in-time (live B regs = 4, not 16)
            #pragma unroll
            for (int g = 0; g < 4; g++) {
                uint32_t bh[4];
                LDSM4(bh, bOff + g * 16 * RSTRIDE + kb);
                #pragma unroll
                for (int f = 0; f < 2; f++) {
                    MMA_F16_F32(acc[f][2 * g + 0], ah[f], bh[0], bh[2]);
                    MMA_F16_F32(acc[f][2 * g + 1], ah[f], bh[1], bh[3]);
                }
            }
        }
        __syncthreads();
    }

    // ------------------------------- epilogue -------------------------------
    const int qrow = lane >> 2;
    const int qcol = (lane & 3) * 2;
    #pragma unroll
    for (int f = 0; f < 2; f++) {
        const int m0 = bm + warp_m * 32 + f * 16 + qrow;
        #pragma unroll
        for (int j = 0; j < 8; j++) {
            const int n = bn + warp_n * 64 + j * 8 + qcol;
            if (OUTMODE == 0) {
                float* Cf = (float*)Cp + (long long)bz * cStr;
                float2 v0 = make_float2(acc[f][j][0], acc[f][j][1]);
                float2 v1 = make_float2(acc[f][j][2], acc[f][j][3]);
                if (bias) {
                    float2 b0 = *(const float2*)(bias + (long long)m0 * Ng + n);
                    float2 b1 = *(const float2*)(bias + (long long)(m0 + 8) * Ng + n);
                    v0.x += b0.x; v0.y += b0.y; v1.x += b1.x; v1.y += b1.y;
                }
                v0.x *= alpha; v0.y *= alpha; v1.x *= alpha; v1.y *= alpha;
                *(float2*)(Cf + (long long)m0 * Ng + n) = v0;
                *(float2*)(Cf + (long long)(m0 + 8) * Ng + n) = v1;
            } else {
                __half* Cb = (__half*)Cp;
                *(__half2*)(Cb + (long long)m0 * Ng + n) = __floats2half2_rn(acc[f][j][0], acc[f][j][1]);
                *(__half2*)(Cb + (long long)(m0 + 8) * Ng + n) = __floats2half2_rn(acc[f][j][2], acc[f][j][3]);
            }
        }
    }
}

// ------- fp32 -> fp16 convert, 4x ILP; grid.y selects (src,dst) pair --------
__global__ __launch_bounds__(256)
void split2_k(const float4* __restrict__ s0, __half* __restrict__ d0,
              const float4* __restrict__ s1, __half* __restrict__ d1)
{
    const float4* src = blockIdx.y ? s1 : s0;
    __half* hi = blockIdx.y ? d1 : d0;
    const int i0 = blockIdx.x * 1024 + threadIdx.x;   // 4 float4 per thread
    float4 x[4];
    #pragma unroll
    for (int j = 0; j < 4; j++) x[j] = src[i0 + j * 256];
    #pragma unroll
    for (int j = 0; j < 4; j++) {
        const int i = i0 + j * 256;
        ((__half2*)hi)[2 * i]     = __floats2half2_rn(x[j].x, x[j].y);
        ((__half2*)hi)[2 * i + 1] = __floats2half2_rn(x[j].z, x[j].w);
    }
}

__global__ __launch_bounds__(256)
void split_k(const float4* __restrict__ src, __half* __restrict__ hi, int n4)
{
    const int i0 = blockIdx.x * 1024 + threadIdx.x;
    float4 x[4];
    #pragma unroll
    for (int j = 0; j < 4; j++) x[j] = src[i0 + j * 256];
    #pragma unroll
    for (int j = 0; j < 4; j++) {
        const int i = i0 + j * 256;
        ((__half2*)hi)[2 * i]     = __floats2half2_rn(x[j].x, x[j].y);
        ((__half2*)hi)[2 * i + 1] = __floats2half2_rn(x[j].z, x[j].w);
    }
}

// --- transpose+convert: dst[c][r]=src[r][c]; grid.z picks batch or pair -----
__global__ __launch_bounds__(256)
void tsplit_k(const float* __restrict__ srcA, __half* __restrict__ dstA,
              const float* __restrict__ srcB, __half* __restrict__ dstB,
              int R, int C, long long sStr, long long dStr)
{
    __shared__ float tile[32][33];
    const float* src; __half* hi;
    if (srcB) { src = blockIdx.z ? srcB : srcA; hi = blockIdx.z ? dstB : dstA; }
    else      { src = srcA + (long long)blockIdx.z * sStr;
                hi  = dstA + (long long)blockIdx.z * dStr; }
    const int c0 = blockIdx.x * 32, r0 = blockIdx.y * 32;
    const int tx = threadIdx.x, ty = threadIdx.y;   // block (32,8)
    #pragma unroll
    for (int i = 0; i < 4; i++)
        tile[ty + i * 8][tx] = src[(long long)(r0 + ty + i * 8) * C + c0 + tx];
    __syncthreads();
    #pragma unroll
    for (int i = 0; i < 4; i++)
        hi[(long long)(c0 + ty + i * 8) * R + r0 + tx] =
            __float2half_rn(tile[tx][ty + i * 8]);
}

// ------------------------------- softmax ------------------------------------
__global__ __launch_bounds__(256)
void softmax_kernel(const float* __restrict__ scores, float* __restrict__ attn_out,
                    __half* __restrict__ ahi)
{
    const size_t row = blockIdx.x;
    const float* p = scores + row * SEQ;
    const int t = threadIdx.x;
    __shared__ float red[8];

    float v[8];
    float mx = -INFINITY;
    #pragma unroll
    for (int i = 0; i < 8; i++) { v[i] = p[t + i * 256]; mx = fmaxf(mx, v[i]); }
    #pragma unroll
    for (int o = 16; o; o >>= 1) mx = fmaxf(mx, __shfl_xor_sync(0xffffffffu, mx, o));
    if ((t & 31) == 0) red[t >> 5] = mx;
    __syncthreads();
    mx = red[0];
    #pragma unroll
    for (int w = 1; w < 8; w++) mx = fmaxf(mx, red[w]);
    __syncthreads();

    float s = 0.f;
    #pragma unroll
    for (int i = 0; i < 8; i++) { v[i] = __expf(v[i] - mx); s += v[i]; }
    #pragma unroll
    for (int o = 16; o; o >>= 1) s += __shfl_xor_sync(0xffffffffu, s, o);
    if ((t & 31) == 0) red[t >> 5] = s;
    __syncthreads();
    s = 0.f;
    #pragma unroll
    for (int w = 0; w < 8; w++) s += red[w];

    const float inv = 1.f / s;
    #pragma unroll
    for (int i = 0; i < 8; i++) {
        const float a = v[i] * inv;
        const size_t idx = row * SEQ + t + i * 256;
        if (attn_out) attn_out[idx] = a;
        if (ahi) ahi[idx] = __float2half_rn(a);
    }
}

// ---------------------------------------------------------------------------
extern "C" void kernel_launch(void* const* d_in, const int* in_sizes, int n_in,
                              void* d_out, int out_size)
{
    const float* q  = (const float*)d_in[0];
    const float* k  = (const float*)d_in[1];
    const float* v  = (const float*)d_in[2];
    const float* pe = (const float*)d_in[3];
    const float* Uq = (const float*)d_in[4];
    const float* Uk = (const float*)d_in[5];
    float* out = (float*)d_out;

    __half *qhi, *khi, *vthi, *ahi;
    __half *pehi, *uqt, *ukt, *qpe, *kpe;
    float *bias, *scores;
    cudaGetSymbolAddress((void**)&qhi,  g_qhi);
    cudaGetSymbolAddress((void**)&khi,  g_khi);
    cudaGetSymbolAddress((void**)&vthi, g_vthi);  cudaGetSymbolAddress((void**)&ahi,  g_ahi);
    cudaGetSymbolAddress((void**)&pehi, g_pehi);
    cudaGetSymbolAddress((void**)&uqt,  g_uqt);   cudaGetSymbolAddress((void**)&ukt,  g_ukt);
    cudaGetSymbolAddress((void**)&qpe,  g_qpe);   cudaGetSymbolAddress((void**)&kpe,  g_kpe);
    cudaGetSymbolAddress((void**)&bias, g_bias);  cudaGetSymbolAddress((void**)&scores, g_scores);

    const float invScale = 1.0f / 11.313708498984761f;  // 1/sqrt(2*64)

    const long long ctxElems  = (long long)NB * SEQ * DM;
    const long long attnElems = (long long)NB * SEQ * SEQ;
    float* ctxOut  = out;
    float* attnOut = nullptr;
    if ((long long)out_size == ctxElems + attnElems) {
        attnOut = out + ctxElems;
    } else if ((long long)out_size == attnElems) {
        attnOut = out; ctxOut = nullptr;
    }

    const int SM1 = 2 * 2 * 128 * 80;   // 40960 B (2 stages x 2 tiles)
    cudaFuncSetAttribute(hgemm<0>, cudaFuncAttributeMaxDynamicSharedMemorySize, SM1);
    cudaFuncSetAttribute(hgemm<1>, cudaFuncAttributeMaxDynamicSharedMemorySize, SM1);

    // ---- converts (q+k fused into one launch; Uq+Uk fused) ----
    split2_k<<<dim3((int)(NQ / 4 / 1024), 2), 256>>>(
        (const float4*)q, qhi, (const float4*)k, khi);
    split_k<<<(int)(NP / 4 / 1024), 256>>>((const float4*)pe, pehi, (int)(NP / 4));
    tsplit_k<<<dim3(DM / 32, DM / 32, 2), dim3(32, 8)>>>(Uq, uqt, Uk, ukt, DM, DM, 0, 0);
    if (ctxOut)
        tsplit_k<<<dim3(DM / 32, SEQ / 32, NB), dim3(32, 8)>>>(
            v, vthi, nullptr, nullptr, SEQ, DM, (long long)SEQ * DM, (long long)SEQ * DM);

    // ---- TUPE bias chain (single-pass fp16) ----
    hgemm<1><<<dim3(DM / 128, SEQ / 128, 1), 256, SM1>>>(
        pehi, uqt, qpe, nullptr, DM, DM, 0, 0, 0, 1.f);
    hgemm<1><<<dim3(DM / 128, SEQ / 128, 1), 256, SM1>>>(
        pehi, ukt, kpe, nullptr, DM, DM, 0, 0, 0, 1.f);
    hgemm<0><<<dim3(SEQ / 128, SEQ / 128, 1), 256, SM1>>>(
        qpe, kpe, bias, nullptr, DM, SEQ, 0, 0, 0, 1.f);

    // ---- scores = (q @ k^T + bias) * invScale  (single-pass fp16) ----
    hgemm<0><<<dim3(SEQ / 128, SEQ / 128, NB), 256, SM1>>>(
        qhi, khi, scores, bias, DM, SEQ,
        (long long)SEQ * DM, (long long)SEQ * DM, (long long)SEQ * SEQ, invScale);

    // ---- softmax (emits attn fp32 and/or fp16) ----
    softmax_kernel<<<NB * SEQ, 256>>>(scores, attnOut, ctxOut ? ahi : nullptr);

    // ---- ctx^T = v^T @ attn^T  (single-pass fp16, row-major out == swapaxes) ----
    if (ctxOut)
        hgemm<0><<<dim3(SEQ / 128, DM / 128, NB), 256, SM1>>>(
            vthi, ahi, ctxOut, nullptr, SEQ, SEQ,
            (long long)SEQ * DM, (long long)SEQ * SEQ, (long long)SEQ * DM, 1.f);
}

// round 16
// speedup vs baseline: 2.0681x; 2.0681x over previous
#include <cuda_runtime.h>
#include <cuda_fp16.h>
#include <math.h>
#include <stdint.h>

#define SEQ 2048
#define DM  1024
#define NB  4

static constexpr size_t NQ  = (size_t)NB * SEQ * DM;    //  8388608
static constexpr size_t NSS = (size_t)NB * SEQ * SEQ;   // 16777216
static constexpr size_t NP  = (size_t)SEQ * DM;         //  2097152
static constexpr size_t NU  = (size_t)DM * DM;          //  1048576

// ---- scratch (static device globals; no allocation) ----
__device__ __half g_qhi[NQ];
__device__ __half g_khi[NQ];
__device__ __half g_vthi[NQ];
__device__ __half g_ahi[NSS];
__device__ __half g_pehi[NP];
__device__ __half g_uqt[NU],  g_ukt[NU];
__device__ __half g_qpe[NP],  g_kpe[NP];
__device__ float  g_bias[(size_t)SEQ * SEQ];
__device__ float  g_scores[NSS];

// ------------------------------- PTX helpers -------------------------------
__device__ __forceinline__ uint32_t s2u(const void* p) {
    uint32_t a;
    asm("{ .reg .u64 t; cvta.to.shared.u64 t, %1; cvt.u32.u64 %0, t; }"
        : "=r"(a) : "l"(p));
    return a;
}
__device__ __forceinline__ void cpa16(uint32_t dst, const void* src) {
    asm volatile("cp.async.cg.shared.global [%0], [%1], 16;" :: "r"(dst), "l"(src) : "memory");
}
#define LDSM4(r, addr) \
    asm volatile("ldmatrix.sync.aligned.m8n8.x4.shared.b16 {%0,%1,%2,%3}, [%4];" \
        : "=r"((r)[0]), "=r"((r)[1]), "=r"((r)[2]), "=r"((r)[3]) : "r"(addr))
#define MMA_F16_F32(d, a, b0, b1) \
    asm volatile("mma.sync.aligned.m16n8k16.row.col.f32.f16.f16.f32 " \
        "{%0,%1,%2,%3}, {%4,%5,%6,%7}, {%8,%9}, {%0,%1,%2,%3};" \
        : "+f"((d)[0]), "+f"((d)[1]), "+f"((d)[2]), "+f"((d)[3]) \
        : "r"((a)[0]), "r"((a)[1]), "r"((a)[2]), "r"((a)[3]), "r"(b0), "r"(b1))

// ---------------------------------------------------------------------------
// fp16 HMMA GEMM (single pass): C[M,N] = alpha * (A @ B^T [+ bias])
//   OUTMODE: 0 = fp32 row-major (+bias, *alpha); 1 = fp16 row-major
//   CTA tile 128x128, BK=32, 256 threads (8 warps, warp tile 32x64),
//   2-stage cp.async pipeline, 80B-padded SMEM rows (conflict-free ldmatrix),
//   2 CTAs/SM (R14-proven config: no spills, 4 warps/SMSP HMMA interleave).
// ---------------------------------------------------------------------------
template<int OUTMODE>
__global__ void __launch_bounds__(256, 2)
hgemm(const __half* __restrict__ A, const __half* __restrict__ B,
      void* __restrict__ Cp, const float* __restrict__ bias, int Kt, int Ng,
      long long aStr, long long bStr, long long cStr, float alpha)
{
    extern __shared__ __align__(128) char smem[];
    constexpr int RSTRIDE = 80;                     // 32 f16 + 16B pad
    constexpr int TSZ = 128 * RSTRIDE;              // 10240 B per tile
    constexpr int STAGE = 2 * TSZ;

    const uint32_t sb = s2u(smem);
    const int tid = threadIdx.x;
    const int lane = tid & 31;
    const int wid = tid >> 5;
    const int warp_m = wid & 3;                      // 4 warps along M
    const int warp_n = wid >> 2;                     // 2 warps along N
    const int bm = blockIdx.y * 128, bn = blockIdx.x * 128, bz = blockIdx.z;
    const int NC = Kt >> 5;                          // chunks of BK=32

    const __half* Ab = A + (long long)bz * aStr;
    const __half* Bb = B + (long long)bz * bStr;

    auto load_chunk = [&](int c) {
        const uint32_t stg = sb + (c & 1) * STAGE;
        const long long kc = (long long)c << 5;
        #pragma unroll
        for (int it = 0; it < 4; it++) {
            const int idx = tid + it * 256;          // 1024 chunks of 16B
            const int t4  = idx >> 9;                // 0=A, 1=B
            const int r   = (idx >> 2) & 127;        // row in tile
            const int c16 = idx & 3;                 // 16B chunk in row
            const __half* src = t4 ? Bb : Ab;
            const int rowg = (t4 ? bn : bm) + r;
            cpa16(stg + t4 * TSZ + r * RSTRIDE + c16 * 16,
                  src + (long long)rowg * Kt + kc + c16 * 8);
        }
        asm volatile("cp.async.commit_group;" ::: "memory");
    };

    float acc[2][8][4];
    #pragma unroll
    for (int f = 0; f < 2; f++)
        #pragma unroll
        for (int j = 0; j < 8; j++)
            #pragma unroll
            for (int e = 0; e < 4; e++) acc[f][j][e] = 0.f;

    load_chunk(0);

    const int lrow = lane & 15;
    const int lkof = (lane >> 4) * 16;               // bytes

    for (int c = 0; c < NC; c++) {
        if (c + 1 < NC) {
            load_chunk(c + 1);
            asm volatile("cp.async.wait_group 1;" ::: "memory");
        } else {
            asm volatile("cp.async.wait_group 0;" ::: "memory");
        }
        __syncthreads();
        const uint32_t stg = sb + (c & 1) * STAGE;
        const uint32_t aOff = stg + (warp_m * 32 + lrow) * RSTRIDE + lkof;
        const uint32_t bOff = stg + TSZ + (warp_n * 64 + lrow) * RSTRIDE + lkof;
        #pragma unroll
        for (int ks = 0; ks < 2; ks++) {
            const uint32_t kb = ks * 32;             // 16 elems = 32 bytes
            uint32_t ah[2][4], bh[4][4];
            #pragma unroll
            for (int f = 0; f < 2; f++) LDSM4(ah[f], aOff + f * 16 * RSTRIDE + kb);
            #pragma unroll
            for (int g = 0; g < 4; g++) LDSM4(bh[g], bOff + g * 16 * RSTRIDE + kb);
            #pragma unroll
            for (int f = 0; f < 2; f++)
                #pragma unroll
                for (int g = 0; g < 4; g++) {
                    MMA_F16_F32(acc[f][2 * g + 0], ah[f], bh[g][0], bh[g][2]);
                    MMA_F16_F32(acc[f][2 * g + 1], ah[f], bh[g][1], bh[g][3]);
                }
        }
        __syncthreads();
    }

    // ------------------------------- epilogue -------------------------------
    const int qrow = lane >> 2;
    const int qcol = (lane & 3) * 2;
    #pragma unroll
    for (int f = 0; f < 2; f++) {
        const int m0 = bm + warp_m * 32 + f * 16 + qrow;
        #pragma unroll
        for (int j = 0; j < 8; j++) {
            const int n = bn + warp_n * 64 + j * 8 + qcol;
            if (OUTMODE == 0) {
                float* Cf = (float*)Cp + (long long)bz * cStr;
                float2 v0 = make_float2(acc[f][j][0], acc[f][j][1]);
                float2 v1 = make_float2(acc[f][j][2], acc[f][j][3]);
                if (bias) {
                    float2 b0 = *(const float2*)(bias + (long long)m0 * Ng + n);
                    float2 b1 = *(const float2*)(bias + (long long)(m0 + 8) * Ng + n);
                    v0.x += b0.x; v0.y += b0.y; v1.x += b1.x; v1.y += b1.y;
                }
                v0.x *= alpha; v0.y *= alpha; v1.x *= alpha; v1.y *= alpha;
                *(float2*)(Cf + (long long)m0 * Ng + n) = v0;
                *(float2*)(Cf + (long long)(m0 + 8) * Ng + n) = v1;
            } else {
                __half* Cb = (__half*)Cp + (long long)bz * cStr;
                *(__half2*)(Cb + (long long)m0 * Ng + n) = __floats2half2_rn(acc[f][j][0], acc[f][j][1]);
                *(__half2*)(Cb + (long long)(m0 + 8) * Ng + n) = __floats2half2_rn(acc[f][j][2], acc[f][j][3]);
            }
        }
    }
}

// ------- fp32 -> fp16 convert, 4x ILP; grid.y selects (src,dst) pair --------
__global__ __launch_bounds__(256)
void split2_k(const float4* __restrict__ s0, __half* __restrict__ d0,
              const float4* __restrict__ s1, __half* __restrict__ d1)
{
    const float4* src = blockIdx.y ? s1 : s0;
    __half* hi = blockIdx.y ? d1 : d0;
    const int i0 = blockIdx.x * 1024 + threadIdx.x;   // 4 float4 per thread
    float4 x[4];
    #pragma unroll
    for (int j = 0; j < 4; j++) x[j] = src[i0 + j * 256];
    #pragma unroll
    for (int j = 0; j < 4; j++) {
        const int i = i0 + j * 256;
        ((__half2*)hi)[2 * i]     = __floats2half2_rn(x[j].x, x[j].y);
        ((__half2*)hi)[2 * i + 1] = __floats2half2_rn(x[j].z, x[j].w);
    }
}

__global__ __launch_bounds__(256)
void split_k(const float4* __restrict__ src, __half* __restrict__ hi, int n4)
{
    const int i0 = blockIdx.x * 1024 + threadIdx.x;
    float4 x[4];
    #pragma unroll
    for (int j = 0; j < 4; j++) x[j] = src[i0 + j * 256];
    #pragma unroll
    for (int j = 0; j < 4; j++) {
        const int i = i0 + j * 256;
        ((__half2*)hi)[2 * i]     = __floats2half2_rn(x[j].x, x[j].y);
        ((__half2*)hi)[2 * i + 1] = __floats2half2_rn(x[j].z, x[j].w);
    }
}

// --- transpose+convert: dst[c][r]=src[r][c]; grid.z picks batch or pair -----
__global__ __launch_bounds__(256)
void tsplit_k(const float* __restrict__ srcA, __half* __restrict__ dstA,
              const float* __restrict__ srcB, __half* __restrict__ dstB,
              int R, int C, long long sStr, long long dStr)
{
    __shared__ float tile[32][33];
    const float* src; __half* hi;
    if (srcB) { src = blockIdx.z ? srcB : srcA; hi = blockIdx.z ? dstB : dstA; }
    else      { src = srcA + (long long)blockIdx.z * sStr;
                hi  = dstA + (long long)blockIdx.z * dStr; }
    const int c0 = blockIdx.x * 32, r0 = blockIdx.y * 32;
    const int tx = threadIdx.x, ty = threadIdx.y;   // block (32,8)
    #pragma unroll
    for (int i = 0; i < 4; i++)
        tile[ty + i * 8][tx] = src[(long long)(r0 + ty + i * 8) * C + c0 + tx];
    __syncthreads();
    #pragma unroll
    for (int i = 0; i < 4; i++)
        hi[(long long)(c0 + ty + i * 8) * R + r0 + tx] =
            __float2half_rn(tile[tx][ty + i * 8]);
}

// ------------------------------- softmax ------------------------------------
__global__ __launch_bounds__(256)
void softmax_kernel(const float* __restrict__ scores, float* __restrict__ attn_out,
                    __half* __restrict__ ahi)
{
    const size_t row = blockIdx.x;
    const float* p = scores + row * SEQ;
    const int t = threadIdx.x;
    __shared__ float red[8];

    float v[8];
    float mx = -INFINITY;
    #pragma unroll
    for (int i = 0; i < 8; i++) { v[i] = p[t + i * 256]; mx = fmaxf(mx, v[i]); }
    #pragma unroll
    for (int o = 16; o; o >>= 1) mx = fmaxf(mx, __shfl_xor_sync(0xffffffffu, mx, o));
    if ((t & 31) == 0) red[t >> 5] = mx;
    __syncthreads();
    mx = red[0];
    #pragma unroll
    for (int w = 1; w < 8; w++) mx = fmaxf(mx, red[w]);
    __syncthreads();

    float s = 0.f;
    #pragma unroll
    for (int i = 0; i < 8; i++) { v[i] = __expf(v[i] - mx); s += v[i]; }
    #pragma unroll
    for (int o = 16; o; o >>= 1) s += __shfl_xor_sync(0xffffffffu, s, o);
    if ((t & 31) == 0) red[t >> 5] = s;
    __syncthreads();
    s = 0.f;
    #pragma unroll
    for (int w = 0; w < 8; w++) s += red[w];

    const float inv = 1.f / s;
    #pragma unroll
    for (int i = 0; i < 8; i++) {
        const float a = v[i] * inv;
        const size_t idx = row * SEQ + t + i * 256;
        if (attn_out) attn_out[idx] = a;
        if (ahi) ahi[idx] = __float2half_rn(a);
    }
}

// ---------------------------------------------------------------------------
extern "C" void kernel_launch(void* const* d_in, const int* in_sizes, int n_in,
                              void* d_out, int out_size)
{
    const float* q  = (const float*)d_in[0];
    const float* k  = (const float*)d_in[1];
    const float* v  = (const float*)d_in[2];
    const float* pe = (const float*)d_in[3];
    const float* Uq = (const float*)d_in[4];
    const float* Uk = (const float*)d_in[5];
    float* out = (float*)d_out;

    __half *qhi, *khi, *vthi, *ahi;
    __half *pehi, *uqt, *ukt, *qpe, *kpe;
    float *bias, *scores;
    cudaGetSymbolAddress((void**)&qhi,  g_qhi);
    cudaGetSymbolAddress((void**)&khi,  g_khi);
    cudaGetSymbolAddress((void**)&vthi, g_vthi);  cudaGetSymbolAddress((void**)&ahi,  g_ahi);
    cudaGetSymbolAddress((void**)&pehi, g_pehi);
    cudaGetSymbolAddress((void**)&uqt,  g_uqt);   cudaGetSymbolAddress((void**)&ukt,  g_ukt);
    cudaGetSymbolAddress((void**)&qpe,  g_qpe);   cudaGetSymbolAddress((void**)&kpe,  g_kpe);
    cudaGetSymbolAddress((void**)&bias, g_bias);  cudaGetSymbolAddress((void**)&scores, g_scores);

    const float invScale = 1.0f / 11.313708498984761f;  // 1/sqrt(2*64)

    const long long ctxElems  = (long long)NB * SEQ * DM;
    const long long attnElems = (long long)NB * SEQ * SEQ;
    float* ctxOut  = out;
    float* attnOut = nullptr;
    if ((long long)out_size == ctxElems + attnElems) {
        attnOut = out + ctxElems;
    } else if ((long long)out_size == attnElems) {
        attnOut = out; ctxOut = nullptr;
    }

    const int SM1 = 2 * 2 * 128 * 80;   // 40960 B (2 stages x 2 tiles)
    cudaFuncSetAttribute(hgemm<0>, cudaFuncAttributeMaxDynamicSharedMemorySize, SM1);
    cudaFuncSetAttribute(hgemm<1>, cudaFuncAttributeMaxDynamicSharedMemorySize, SM1);

    // ---- converts (q+k fused; Uq+Uk fused) ----
    split2_k<<<dim3((int)(NQ / 4 / 1024), 2), 256>>>(
        (const float4*)q, qhi, (const float4*)k, khi);
    split_k<<<(int)(NP / 4 / 1024), 256>>>((const float4*)pe, pehi, (int)(NP / 4));
    tsplit_k<<<dim3(DM / 32, DM / 32, 2), dim3(32, 8)>>>(Uq, uqt, Uk, ukt, DM, DM, 0, 0);
    if (ctxOut)
        tsplit_k<<<dim3(DM / 32, SEQ / 32, NB), dim3(32, 8)>>>(
            v, vthi, nullptr, nullptr, SEQ, DM, (long long)SEQ * DM, (long long)SEQ * DM);

    // ---- TUPE bias chain: qpe & kpe batched via stride trick (z = 0/1) ----
    hgemm<1><<<dim3(DM / 128, SEQ / 128, 2), 256, SM1>>>(
        pehi, uqt, qpe, nullptr, DM, DM,
        0, (long long)(ukt - uqt), (long long)(kpe - qpe), 1.f);
    hgemm<0><<<dim3(SEQ / 128, SEQ / 128, 1), 256, SM1>>>(
        qpe, kpe, bias, nullptr, DM, SEQ, 0, 0, 0, 1.f);

    // ---- scores = (q @ k^T + bias) * invScale  (single-pass fp16) ----
    hgemm<0><<<dim3(SEQ / 128, SEQ / 128, NB), 256, SM1>>>(
        qhi, khi, scores, bias, DM, SEQ,
        (long long)SEQ * DM, (long long)SEQ * DM, (long long)SEQ * SEQ, invScale);

    // ---- softmax (emits attn fp32 and/or fp16) ----
    softmax_kernel<<<NB * SEQ, 256>>>(scores, attnOut, ctxOut ? ahi : nullptr);

    // ---- ctx^T = v^T @ attn^T  (single-pass fp16, row-major out == swapaxes) ----
    if (ctxOut)
        hgemm<0><<<dim3(SEQ / 128, DM / 128, NB), 256, SM1>>>(
            vthi, ahi, ctxOut, nullptr, SEQ, SEQ,
            (long long)SEQ * DM, (long long)SEQ * SEQ, (long long)SEQ * DM, 1.f);
}

// round 17
// speedup vs baseline: 2.3247x; 1.1241x over previous
#include <cuda_runtime.h>
#include <cuda_fp16.h>
#include <math.h>
#include <stdint.h>

#define SEQ 2048
#define DM  1024
#define NB  4

static constexpr size_t NQ  = (size_t)NB * SEQ * DM;    //  8388608
static constexpr size_t NSS = (size_t)NB * SEQ * SEQ;   // 16777216
static constexpr size_t NP  = (size_t)SEQ * DM;         //  2097152
static constexpr size_t NU  = (size_t)DM * DM;          //  1048576

// ---- scratch (static device globals; no allocation) ----
__device__ __half g_qhi[NQ];
__device__ __half g_khi[NQ];
__device__ __half g_vthi[NQ];
__device__ __half g_ahi[NSS];
__device__ __half g_pehi[NP];
__device__ __half g_uqt[NU],  g_ukt[NU];
__device__ __half g_qpe[NP],  g_kpe[NP];
__device__ float  g_bias[(size_t)SEQ * SEQ];
__device__ float  g_scores[NSS];

// ------------------------------- PTX helpers -------------------------------
__device__ __forceinline__ uint32_t s2u(const void* p) {
    uint32_t a;
    asm("{ .reg .u64 t; cvta.to.shared.u64 t, %1; cvt.u32.u64 %0, t; }"
        : "=r"(a) : "l"(p));
    return a;
}
__device__ __forceinline__ void cpa16(uint32_t dst, const void* src) {
    asm volatile("cp.async.cg.shared.global [%0], [%1], 16;" :: "r"(dst), "l"(src) : "memory");
}
#define LDSM4(r, addr) \
    asm volatile("ldmatrix.sync.aligned.m8n8.x4.shared.b16 {%0,%1,%2,%3}, [%4];" \
        : "=r"((r)[0]), "=r"((r)[1]), "=r"((r)[2]), "=r"((r)[3]) : "r"(addr))
#define MMA_F16_F32(d, a, b0, b1) \
    asm volatile("mma.sync.aligned.m16n8k16.row.col.f32.f16.f16.f32 " \
        "{%0,%1,%2,%3}, {%4,%5,%6,%7}, {%8,%9}, {%0,%1,%2,%3};" \
        : "+f"((d)[0]), "+f"((d)[1]), "+f"((d)[2]), "+f"((d)[3]) \
        : "r"((a)[0]), "r"((a)[1]), "r"((a)[2]), "r"((a)[3]), "r"(b0), "r"(b1))

// ---------------------------------------------------------------------------
// fp16 HMMA GEMM (single pass): C[M,N] = alpha * (A @ B^T [+ bias])
//   OUTMODE: 0 = fp32 row-major (+bias, *alpha); 1 = fp16 row-major
//   CTA tile 128x128, BK=64 (128B rows, 144B padded stride — conflict-free
//   ldmatrix: r*144 mod 128 covers all eight 16B granules), 256 threads
//   (8 warps, warp tile 32x64), 2-stage cp.async pipeline, 2 CTAs/SM.
// ---------------------------------------------------------------------------
template<int OUTMODE>
__global__ void __launch_bounds__(256, 2)
hgemm(const __half* __restrict__ A, const __half* __restrict__ B,
      void* __restrict__ Cp, const float* __restrict__ bias, int Kt, int Ng,
      long long aStr, long long bStr, long long cStr, float alpha)
{
    extern __shared__ __align__(128) char smem[];
    constexpr int RSTRIDE = 144;                    // 64 f16 (128B) + 16B pad
    constexpr int TSZ = 128 * RSTRIDE;              // 18432 B per tile
    constexpr int STAGE = 2 * TSZ;                  // 36864 B

    const uint32_t sb = s2u(smem);
    const int tid = threadIdx.x;
    const int lane = tid & 31;
    const int wid = tid >> 5;
    const int warp_m = wid & 3;                      // 4 warps along M
    const int warp_n = wid >> 2;                     // 2 warps along N
    const int bm = blockIdx.y * 128, bn = blockIdx.x * 128, bz = blockIdx.z;
    const int NC = Kt >> 6;                          // chunks of BK=64

    const __half* Ab = A + (long long)bz * aStr;
    const __half* Bb = B + (long long)bz * bStr;

    auto load_chunk = [&](int c) {
        const uint32_t stg = sb + (c & 1) * STAGE;
        const long long kc = (long long)c << 6;
        #pragma unroll
        for (int it = 0; it < 8; it++) {
            const int idx = tid + it * 256;          // 2048 chunks of 16B
            const int t4  = idx >> 10;               // 0=A, 1=B
            const int r   = (idx >> 3) & 127;        // row in tile
            const int c16 = idx & 7;                 // 16B chunk in 128B row
            const __half* src = t4 ? Bb : Ab;
            const int rowg = (t4 ? bn : bm) + r;
            cpa16(stg + t4 * TSZ + r * RSTRIDE + c16 * 16,
                  src + (long long)rowg * Kt + kc + c16 * 8);
        }
        asm volatile("cp.async.commit_group;" ::: "memory");
    };

    float acc[2][8][4];
    #pragma unroll
    for (int f = 0; f < 2; f++)
        #pragma unroll
        for (int j = 0; j < 8; j++)
            #pragma unroll
            for (int e = 0; e < 4; e++) acc[f][j][e] = 0.f;

    load_chunk(0);

    const int lrow = lane & 15;
    const int lkof = (lane >> 4) * 16;               // bytes

    for (int c = 0; c < NC; c++) {
        if (c + 1 < NC) {
            load_chunk(c + 1);
            asm volatile("cp.async.wait_group 1;" ::: "memory");
        } else {
            asm volatile("cp.async.wait_group 0;" ::: "memory");
        }
        __syncthreads();
        const uint32_t stg = sb + (c & 1) * STAGE;
        const uint32_t aOff = stg + (warp_m * 32 + lrow) * RSTRIDE + lkof;
        const uint32_t bOff = stg + TSZ + (warp_n * 64 + lrow) * RSTRIDE + lkof;
        #pragma unroll
        for (int ks = 0; ks < 4; ks++) {             // 4 k16 steps per 64-K chunk
            const uint32_t kb = ks * 32;             // 16 elems = 32 bytes
            uint32_t ah[2][4], bh[4][4];
            #pragma unroll
            for (int f = 0; f < 2; f++) LDSM4(ah[f], aOff + f * 16 * RSTRIDE + kb);
            #pragma unroll
            for (int g = 0; g < 4; g++) LDSM4(bh[g], bOff + g * 16 * RSTRIDE + kb);
            #pragma unroll
            for (int f = 0; f < 2; f++)
                #pragma unroll
                for (int g = 0; g < 4; g++) {
                    MMA_F16_F32(acc[f][2 * g + 0], ah[f], bh[g][0], bh[g][2]);
                    MMA_F16_F32(acc[f][2 * g + 1], ah[f], bh[g][1], bh[g][3]);
                }
        }
        __syncthreads();
    }

    // ------------------------------- epilogue -------------------------------
    const int qrow = lane >> 2;
    const int qcol = (lane & 3) * 2;
    #pragma unroll
    for (int f = 0; f < 2; f++) {
        const int m0 = bm + warp_m * 32 + f * 16 + qrow;
        #pragma unroll
        for (int j = 0; j < 8; j++) {
            const int n = bn + warp_n * 64 + j * 8 + qcol;
            if (OUTMODE == 0) {
                float* Cf = (float*)Cp + (long long)bz * cStr;
                float2 v0 = make_float2(acc[f][j][0], acc[f][j][1]);
                float2 v1 = make_float2(acc[f][j][2], acc[f][j][3]);
                if (bias) {
                    float2 b0 = *(const float2*)(bias + (long long)m0 * Ng + n);
                    float2 b1 = *(const float2*)(bias + (long long)(m0 + 8) * Ng + n);
                    v0.x += b0.x; v0.y += b0.y; v1.x += b1.x; v1.y += b1.y;
                }
                v0.x *= alpha; v0.y *= alpha; v1.x *= alpha; v1.y *= alpha;
                *(float2*)(Cf + (long long)m0 * Ng + n) = v0;
                *(float2*)(Cf + (long long)(m0 + 8) * Ng + n) = v1;
            } else {
                __half* Cb = (__half*)Cp + (long long)bz * cStr;
                *(__half2*)(Cb + (long long)m0 * Ng + n) = __floats2half2_rn(acc[f][j][0], acc[f][j][1]);
                *(__half2*)(Cb + (long long)(m0 + 8) * Ng + n) = __floats2half2_rn(acc[f][j][2], acc[f][j][3]);
            }
        }
    }
}

// ------- fp32 -> fp16 convert, 4x ILP; grid.y selects (src,dst) pair --------
__global__ __launch_bounds__(256)
void split2_k(const float4* __restrict__ s0, __half* __restrict__ d0,
              const float4* __restrict__ s1, __half* __restrict__ d1)
{
    const float4* src = blockIdx.y ? s1 : s0;
    __half* hi = blockIdx.y ? d1 : d0;
    const int i0 = blockIdx.x * 1024 + threadIdx.x;   // 4 float4 per thread
    float4 x[4];
    #pragma unroll
    for (int j = 0; j < 4; j++) x[j] = src[i0 + j * 256];
    #pragma unroll
    for (int j = 0; j < 4; j++) {
        const int i = i0 + j * 256;
        ((__half2*)hi)[2 * i]     = __floats2half2_rn(x[j].x, x[j].y);
        ((__half2*)hi)[2 * i + 1] = __floats2half2_rn(x[j].z, x[j].w);
    }
}

__global__ __launch_bounds__(256)
void split_k(const float4* __restrict__ src, __half* __restrict__ hi, int n4)
{
    const int i0 = blockIdx.x * 1024 + threadIdx.x;
    float4 x[4];
    #pragma unroll
    for (int j = 0; j < 4; j++) x[j] = src[i0 + j * 256];
    #pragma unroll
    for (int j = 0; j < 4; j++) {
        const int i = i0 + j * 256;
        ((__half2*)hi)[2 * i]     = __floats2half2_rn(x[j].x, x[j].y);
        ((__half2*)hi)[2 * i + 1] = __floats2half2_rn(x[j].z, x[j].w);
    }
}

// --- transpose+convert: dst[c][r]=src[r][c]; grid.z picks batch or pair -----
__global__ __launch_bounds__(256)
void tsplit_k(const float* __restrict__ srcA, __half* __restrict__ dstA,
              const float* __restrict__ srcB, __half* __restrict__ dstB,
              int R, int C, long long sStr, long long dStr)
{
    __shared__ float tile[32][33];
    const float* src; __half* hi;
    if (srcB) { src = blockIdx.z ? srcB : srcA; hi = blockIdx.z ? dstB : dstA; }
    else      { src = srcA + (long long)blockIdx.z * sStr;
                hi  = dstA + (long long)blockIdx.z * dStr; }
    const int c0 = blockIdx.x * 32, r0 = blockIdx.y * 32;
    const int tx = threadIdx.x, ty = threadIdx.y;   // block (32,8)
    #pragma unroll
    for (int i = 0; i < 4; i++)
        tile[ty + i * 8][tx] = src[(long long)(r0 + ty + i * 8) * C + c0 + tx];
    __syncthreads();
    #pragma unroll
    for (int i = 0; i < 4; i++)
        hi[(long long)(c0 + ty + i * 8) * R + r0 + tx] =
            __float2half_rn(tile[tx][ty + i * 8]);
}

// ------------------------------- softmax ------------------------------------
__global__ __launch_bounds__(256)
void softmax_kernel(const float* __restrict__ scores, float* __restrict__ attn_out,
                    __half* __restrict__ ahi)
{
    const size_t row = blockIdx.x;
    const float* p = scores + row * SEQ;
    const int t = threadIdx.x;
    __shared__ float red[8];

    float v[8];
    float mx = -INFINITY;
    #pragma unroll
    for (int i = 0; i < 8; i++) { v[i] = p[t + i * 256]; mx = fmaxf(mx, v[i]); }
    #pragma unroll
    for (int o = 16; o; o >>= 1) mx = fmaxf(mx, __shfl_xor_sync(0xffffffffu, mx, o));
    if ((t & 31) == 0) red[t >> 5] = mx;
    __syncthreads();
    mx = red[0];
    #pragma unroll
    for (int w = 1; w < 8; w++) mx = fmaxf(mx, red[w]);
    __syncthreads();

    float s = 0.f;
    #pragma unroll
    for (int i = 0; i < 8; i++) { v[i] = __expf(v[i] - mx); s += v[i]; }
    #pragma unroll
    for (int o = 16; o; o >>= 1) s += __shfl_xor_sync(0xffffffffu, s, o);
    if ((t & 31) == 0) red[t >> 5] = s;
    __syncthreads();
    s = 0.f;
    #pragma unroll
    for (int w = 0; w < 8; w++) s += red[w];

    const float inv = 1.f / s;
    #pragma unroll
    for (int i = 0; i < 8; i++) {
        const float a = v[i] * inv;
        const size_t idx = row * SEQ + t + i * 256;
        if (attn_out) attn_out[idx] = a;
        if (ahi) ahi[idx] = __float2half_rn(a);
    }
}

// ---------------------------------------------------------------------------
extern "C" void kernel_launch(void* const* d_in, const int* in_sizes, int n_in,
                              void* d_out, int out_size)
{
    const float* q  = (const float*)d_in[0];
    const float* k  = (const float*)d_in[1];
    const float* v  = (const float*)d_in[2];
    const float* pe = (const float*)d_in[3];
    const float* Uq = (const float*)d_in[4];
    const float* Uk = (const float*)d_in[5];
    float* out = (float*)d_out;

    __half *qhi, *khi, *vthi, *ahi;
    __half *pehi, *uqt, *ukt, *qpe, *kpe;
    float *bias, *scores;
    cudaGetSymbolAddress((void**)&qhi,  g_qhi);
    cudaGetSymbolAddress((void**)&khi,  g_khi);
    cudaGetSymbolAddress((void**)&vthi, g_vthi);  cudaGetSymbolAddress((void**)&ahi,  g_ahi);
    cudaGetSymbolAddress((void**)&pehi, g_pehi);
    cudaGetSymbolAddress((void**)&uqt,  g_uqt);   cudaGetSymbolAddress((void**)&ukt,  g_ukt);
    cudaGetSymbolAddress((void**)&qpe,  g_qpe);   cudaGetSymbolAddress((void**)&kpe,  g_kpe);
    cudaGetSymbolAddress((void**)&bias, g_bias);  cudaGetSymbolAddress((void**)&scores, g_scores);

    const float invScale = 1.0f / 11.313708498984761f;  // 1/sqrt(2*64)

    const long long ctxElems  = (long long)NB * SEQ * DM;
    const long long attnElems = (long long)NB * SEQ * SEQ;
    float* ctxOut  = out;
    float* attnOut = nullptr;
    if ((long long)out_size == ctxElems + attnElems) {
        attnOut = out + ctxElems;
    } else if ((long long)out_size == attnElems) {
        attnOut = out; ctxOut = nullptr;
    }

    const int SM1 = 2 * 2 * 128 * 144;   // 73728 B (2 stages x 2 tiles, BK=64)
    cudaFuncSetAttribute(hgemm<0>, cudaFuncAttributeMaxDynamicSharedMemorySize, SM1);
    cudaFuncSetAttribute(hgemm<1>, cudaFuncAttributeMaxDynamicSharedMemorySize, SM1);

    // ---- converts (q+k fused; Uq+Uk fused) ----
    split2_k<<<dim3((int)(NQ / 4 / 1024), 2), 256>>>(
        (const float4*)q, qhi, (const float4*)k, khi);
    split_k<<<(int)(NP / 4 / 1024), 256>>>((const float4*)pe, pehi, (int)(NP / 4));
    tsplit_k<<<dim3(DM / 32, DM / 32, 2), dim3(32, 8)>>>(Uq, uqt, Uk, ukt, DM, DM, 0, 0);
    if (ctxOut)
        tsplit_k<<<dim3(DM / 32, SEQ / 32, NB), dim3(32, 8)>>>(
            v, vthi, nullptr, nullptr, SEQ, DM, (long long)SEQ * DM, (long long)SEQ * DM);

    // ---- TUPE bias chain: qpe & kpe batched via stride trick (z = 0/1) ----
    hgemm<1><<<dim3(DM / 128, SEQ / 128, 2), 256, SM1>>>(
        pehi, uqt, qpe, nullptr, DM, DM,
        0, (long long)(ukt - uqt), (long long)(kpe - qpe), 1.f);
    hgemm<0><<<dim3(SEQ / 128, SEQ / 128, 1), 256, SM1>>>(
        qpe, kpe, bias, nullptr, DM, SEQ, 0, 0, 0, 1.f);

    // ---- scores = (q @ k^T + bias) * invScale  (single-pass fp16) ----
    hgemm<0><<<dim3(SEQ / 128, SEQ / 128, NB), 256, SM1>>>(
        qhi, khi, scores, bias, DM, SEQ,
        (long long)SEQ * DM, (long long)SEQ * DM, (long long)SEQ * SEQ, invScale);

    // ---- softmax (emits attn fp32 and/or fp16) ----
    softmax_kernel<<<NB * SEQ, 256>>>(scores, attnOut, ctxOut ? ahi : nullptr);

    // ---- ctx^T = v^T @ attn^T  (single-pass fp16, row-major out == swapaxes) ----
    if (ctxOut)
        hgemm<0><<<dim3(SEQ / 128, DM / 128, NB), 256, SM1>>>(
            vthi, ahi, ctxOut, nullptr, SEQ, SEQ,
            (long long)SEQ * DM, (long long)SEQ * SEQ, (long long)SEQ * DM, 1.f);
}